// round 10
// baseline (speedup 1.0000x reference)
#include <cuda_runtime.h>

#define NN    384
#define TS    32
#define NT    (NN / TS)      // 12
#define NBLK  (NT * NT)      // 144 < 148 SMs -> co-resident grid barrier safe
#define NG    8              // K-split groups of 64 threads
#define PP    36             // smem row pitch (floats): float4-aligned, conflict-free reads
#define SMEM_FLOATS (2 * 2 * NN * PP)        // P3: A'(768 x PP) + B'(768 x PP)
#define SMEM_BYTES  (SMEM_FLOATS * 4)        // 221184 B < 227KB cap

typedef unsigned long long ull;

// Scratch (device globals: no allocation allowed)
__device__ __align__(16) float g_u[NN * NN];
__device__ __align__(16) float g_W[NN * NN];

// Distributed grid barrier: per-block flags + one release word (monotone epochs)
__device__ unsigned g_flags[NBLK];
__device__ unsigned g_gen;

__device__ __forceinline__ void grid_barrier(unsigned epoch) {
    __syncthreads();
    if (blockIdx.x == 0) {
        int t = threadIdx.x;
        if (t >= 1 && t < NBLK) {
            while (*(volatile unsigned*)&g_flags[t] < epoch) { }
        }
        __syncthreads();
        if (t == 0) {
            __threadfence();
            *(volatile unsigned*)&g_gen = epoch;
        }
    } else {
        if (threadIdx.x == 0) {
            __threadfence();
            *(volatile unsigned*)&g_flags[blockIdx.x] = epoch;
            while (*(volatile unsigned*)&g_gen < epoch) { }
        }
    }
    __syncthreads();
    __threadfence();
}

__device__ __forceinline__ float decode_lam(const void* p) {
    int raw = *(const int*)p;
    unsigned ub = (unsigned)raw;
    if (ub < 0x01000000u) return (float)raw;   // small-int bits (int32/int64 low)
    return __int_as_float(raw);                // float32 bits
}

// Packed fp32x2 (FFMA2 — not emitted by ptxas from C++)
__device__ __forceinline__ void ffma2(ull& d, ull a, ull b) {
    asm("fma.rn.f32x2 %0, %1, %2, %0;" : "+l"(d) : "l"(a), "l"(b));
}
__device__ __forceinline__ ull dup2(float x) {
    ull r; asm("mov.b64 %0, {%1, %1};" : "=l"(r) : "f"(x)); return r;
}
__device__ __forceinline__ float2 upk(ull v) {
    float2 f; asm("mov.b64 {%0, %1}, %2;" : "=f"(f.x), "=f"(f.y) : "l"(v)); return f;
}

extern __shared__ float smem[];   // [Asm: K x PP][Bsm: K x PP], K=384 (P2) / 768 (P3)

// P1: u = (adj>0 && i!=j) ? exp(-lam*dist) : 0
// P2: W = od/S on S = u + offdiag(u@u)
// P3: out = u .* (W + [W | u^T] @ [u^T ; W])  (single K=768 GEMM)
// Full K-slab staged in smem; barrier-free k-loops; 8 K-groups x 64 thr, 4x4 micro.
__global__ __launch_bounds__(512, 1)
void fused_kernel(const float* __restrict__ od,
                  const int*   __restrict__ adj,
                  const float* __restrict__ dist,
                  const void*  __restrict__ lam_p,
                  float*       __restrict__ out) {
    const int tid  = threadIdx.x;
    const int g    = tid >> 6;            // group 0..7
    const int gtid = tid & 63;
    const int tyy = gtid >> 3;            // rows 4*tyy..+3
    const int txx = gtid & 7;             // cols 4*txx..+3
    const int tileX = blockIdx.x % NT;
    const int tileY = blockIdx.x / NT;
    const int rowBlk = tileY * TS;
    const int colBlk = tileX * TS;

    const unsigned base = *(volatile unsigned*)&g_gen;

    const int er  = tid >> 4;             // epilogue row 0..31
    const int ec0 = 2 * (tid & 15);       // epilogue col pair

    float* Bofs2 = smem + NN * PP;        // P2 B base (K=384)
    float* Bofs3 = smem + 2 * NN * PP;    // P3 B base (K=768)
    float* red   = smem;                  // reduction scratch (reused after sync)

    // ---------------- Phase 1: build u (2 elems/thread) ---------------------
    {
        const float lam = decode_lam(lam_p);
        int bidx = blockIdx.x * 1024 + tid * 2;
        int2   a2 = *(const int2*)&adj[bidx];
        float2 d2 = *(const float2*)&dist[bidx];
        int r = bidx / NN;
        int c = bidx - r * NN;
        float2 v;
        v.x = (a2.x > 0 && r != c    ) ? expf(-lam * d2.x) : 0.f;
        v.y = (a2.y > 0 && r != c + 1) ? expf(-lam * d2.y) : 0.f;
        *(float2*)&g_u[bidx] = v;
    }
    grid_barrier(base + 1);

    // ---------------- Phase 2: G = u@u, W epilogue --------------------------
    {
        // Load A^T slab: Asm[k][r] = u[(rowBlk+r)*NN + k]  (lane->r, conflict-free STS)
#pragma unroll
        for (int it = 0; it < 6; ++it) {
            int q = it * 512 + tid;
            int r = q & 31, kq = q >> 5;                 // kq 0..95
            float4 v = *(const float4*)&g_u[(rowBlk + r) * NN + 4 * kq];
            smem[(4 * kq + 0) * PP + r] = v.x;
            smem[(4 * kq + 1) * PP + r] = v.y;
            smem[(4 * kq + 2) * PP + r] = v.z;
            smem[(4 * kq + 3) * PP + r] = v.w;
        }
        // Load B slab: Bsm[k][c] = u[k*NN + colBlk + c]  (coalesced LDG, STS.128)
#pragma unroll
        for (int it = 0; it < 6; ++it) {
            int q = it * 512 + tid;
            int k = q >> 3, cq = q & 7;
            float4 v = *(const float4*)&g_u[k * NN + colBlk + 4 * cq];
            *(float4*)&Bofs2[k * PP + 4 * cq] = v;
        }
        __syncthreads();

        ull acc[2][4];
#pragma unroll
        for (int i = 0; i < 2; ++i)
#pragma unroll
            for (int j = 0; j < 4; ++j) acc[i][j] = 0ull;

        const int k0 = g * 48;
#pragma unroll 8
        for (int k = k0; k < k0 + 48; ++k) {
            ull a01 = *(const ull*)&smem[k * PP + 4 * tyy];
            ull a23 = *(const ull*)&smem[k * PP + 4 * tyy + 2];
            float4 b = *(const float4*)&Bofs2[k * PP + 4 * txx];
            ull b0 = dup2(b.x), b1 = dup2(b.y), b2 = dup2(b.z), b3 = dup2(b.w);
            ffma2(acc[0][0], a01, b0); ffma2(acc[1][0], a23, b0);
            ffma2(acc[0][1], a01, b1); ffma2(acc[1][1], a23, b1);
            ffma2(acc[0][2], a01, b2); ffma2(acc[1][2], a23, b2);
            ffma2(acc[0][3], a01, b3); ffma2(acc[1][3], a23, b3);
        }
        __syncthreads();
        {
            float s[4][4];
#pragma unroll
            for (int c = 0; c < 4; ++c) {
                float2 p = upk(acc[0][c]); s[0][c] = p.x; s[1][c] = p.y;
                float2 q = upk(acc[1][c]); s[2][c] = q.x; s[3][c] = q.y;
            }
#pragma unroll
            for (int r = 0; r < 4; ++r)
                *(float4*)&red[g * 1024 + (4 * tyy + r) * 32 + 4 * txx] =
                    make_float4(s[r][0], s[r][1], s[r][2], s[r][3]);
        }
        __syncthreads();
        {
            float s0 = 0.f, s1 = 0.f;
#pragma unroll
            for (int gg = 0; gg < NG; ++gg) {
                float2 v = *(const float2*)&red[gg * 1024 + er * 32 + ec0];
                s0 += v.x; s1 += v.y;
            }
            int r = rowBlk + er;
            int c0 = colBlk + ec0;
            int idx = r * NN + c0;
            float2 uv  = *(const float2*)&g_u[idx];
            float2 odv = *(const float2*)&od[idx];
            float S0 = uv.x + ((r != c0)     ? s0 : 0.f);
            float S1 = uv.y + ((r != c0 + 1) ? s1 : 0.f);
            float2 w2;
            w2.x = (odv.x > 0.f && r != c0     && S0 > 0.f) ? (odv.x / S0) : 0.f;
            w2.y = (odv.y > 0.f && r != c0 + 1 && S1 > 0.f) ? (odv.y / S1) : 0.f;
            *(float2*)&g_W[idx] = w2;
        }
    }
    grid_barrier(base + 2);

    // ---------------- Phase 3: C = [W | u^T] @ [u^T ; W], K=768 -------------
    {
        // A' first half: Asm[k][r] = W[(rowBlk+r)*NN + k]  (transposed)
#pragma unroll
        for (int it = 0; it < 6; ++it) {
            int q = it * 512 + tid;
            int r = q & 31, kq = q >> 5;
            float4 v = *(const float4*)&g_W[(rowBlk + r) * NN + 4 * kq];
            smem[(4 * kq + 0) * PP + r] = v.x;
            smem[(4 * kq + 1) * PP + r] = v.y;
            smem[(4 * kq + 2) * PP + r] = v.z;
            smem[(4 * kq + 3) * PP + r] = v.w;
        }
        // A' second half: Asm[384+k][r] = u[k*NN + rowBlk + r]  (natural)
#pragma unroll
        for (int it = 0; it < 6; ++it) {
            int q = it * 512 + tid;
            int k = q >> 3, rq = q & 7;
            float4 v = *(const float4*)&g_u[k * NN + rowBlk + 4 * rq];
            *(float4*)&smem[(NN + k) * PP + 4 * rq] = v;
        }
        // B' first half: Bsm[k][c] = u[(colBlk+c)*NN + k]  (transposed)
#pragma unroll
        for (int it = 0; it < 6; ++it) {
            int q = it * 512 + tid;
            int c = q & 31, kq = q >> 5;
            float4 v = *(const float4*)&g_u[(colBlk + c) * NN + 4 * kq];
            Bofs3[(4 * kq + 0) * PP + c] = v.x;
            Bofs3[(4 * kq + 1) * PP + c] = v.y;
            Bofs3[(4 * kq + 2) * PP + c] = v.z;
            Bofs3[(4 * kq + 3) * PP + c] = v.w;
        }
        // B' second half: Bsm[384+k][c] = W[k*NN + colBlk + c]  (natural)
#pragma unroll
        for (int it = 0; it < 6; ++it) {
            int q = it * 512 + tid;
            int k = q >> 3, cq = q & 7;
            float4 v = *(const float4*)&g_W[k * NN + colBlk + 4 * cq];
            *(float4*)&Bofs3[(NN + k) * PP + 4 * cq] = v;
        }
        __syncthreads();

        ull acc[2][4];
#pragma unroll
        for (int i = 0; i < 2; ++i)
#pragma unroll
            for (int j = 0; j < 4; ++j) acc[i][j] = 0ull;

        const int k0 = g * 96;
#pragma unroll 8
        for (int k = k0; k < k0 + 96; ++k) {
            ull a01 = *(const ull*)&smem[k * PP + 4 * tyy];
            ull a23 = *(const ull*)&smem[k * PP + 4 * tyy + 2];
            float4 b = *(const float4*)&Bofs3[k * PP + 4 * txx];
            ull b0 = dup2(b.x), b1 = dup2(b.y), b2 = dup2(b.z), b3 = dup2(b.w);
            ffma2(acc[0][0], a01, b0); ffma2(acc[1][0], a23, b0);
            ffma2(acc[0][1], a01, b1); ffma2(acc[1][1], a23, b1);
            ffma2(acc[0][2], a01, b2); ffma2(acc[1][2], a23, b2);
            ffma2(acc[0][3], a01, b3); ffma2(acc[1][3], a23, b3);
        }
        __syncthreads();
        {
            float s[4][4];
#pragma unroll
            for (int c = 0; c < 4; ++c) {
                float2 p = upk(acc[0][c]); s[0][c] = p.x; s[1][c] = p.y;
                float2 q = upk(acc[1][c]); s[2][c] = q.x; s[3][c] = q.y;
            }
#pragma unroll
            for (int r = 0; r < 4; ++r)
                *(float4*)&red[g * 1024 + (4 * tyy + r) * 32 + 4 * txx] =
                    make_float4(s[r][0], s[r][1], s[r][2], s[r][3]);
        }
        __syncthreads();
        {
            float s0 = 0.f, s1 = 0.f;
#pragma unroll
            for (int gg = 0; gg < NG; ++gg) {
                float2 v = *(const float2*)&red[gg * 1024 + er * 32 + ec0];
                s0 += v.x; s1 += v.y;
            }
            int r = rowBlk + er;
            int c0 = colBlk + ec0;
            int idx = r * NN + c0;
            float2 uv = *(const float2*)&g_u[idx];
            float2 wv = *(const float2*)&g_W[idx];
            float2 o;
            o.x = uv.x * (wv.x + s0);
            o.y = uv.y * (wv.y + s1);
            *(float2*)&out[idx] = o;
        }
    }
}

extern "C" void kernel_launch(void* const* d_in, const int* in_sizes, int n_in,
                              void* d_out, int out_size) {
    const float* od   = (const float*)d_in[0];
    const int*   adj  = (const int*)d_in[1];
    const float* dist = (const float*)d_in[2];
    const void*  lamp = d_in[3];
    float* out = (float*)d_out;

    cudaFuncSetAttribute(fused_kernel,
                         cudaFuncAttributeMaxDynamicSharedMemorySize, SMEM_BYTES);
    fused_kernel<<<NBLK, 512, SMEM_BYTES>>>(od, adj, dist, lamp, out);
}